// round 11
// baseline (speedup 1.0000x reference)
#include <cuda_runtime.h>
#include <cstdint>

static constexpr int W       = 2048;
static constexpr int PAD     = 24;                 // >= 21 + strip slack
static constexpr int PSTRIDE = W + 2 * PAD;        // 2096 rows per plane
static constexpr unsigned PADVAL = 60000;          // 60000 + 841 < 65535
static constexpr int R       = 8;                  // vpass rows per thread
static constexpr int PX      = 4;                  // vpass pixels per thread
static constexpr int HR      = 4;                  // hpass rows per block

__device__ unsigned short g_dh2[4ULL * PSTRIDE * W];   // ~34 MB squared horiz dist (u16)

// ---- SIMD u16x2 helpers ----
__device__ __forceinline__ unsigned vadd2(unsigned a, unsigned b)
{ unsigned r; asm("add.u16x2 %0,%1,%2;" : "=r"(r) : "r"(a), "r"(b)); return r; }
__device__ __forceinline__ unsigned vmin2(unsigned a, unsigned b)
{ unsigned r; asm("min.u16x2 %0,%1,%2;" : "=r"(r) : "r"(a), "r"(b)); return r; }
__device__ __forceinline__ unsigned vmax2(unsigned a, unsigned b)
{ unsigned r; asm("max.u16x2 %0,%1,%2;" : "=r"(r) : "r"(a), "r"(b)); return r; }

__device__ __forceinline__ void relax2(unsigned acc[2], const uint2& v, unsigned dd)
{
    const unsigned dd2 = dd * 0x00010001u;
    acc[0] = vmin2(acc[0], vadd2(v.x, dd2));
    acc[1] = vmin2(acc[1], vadd2(v.y, dd2));
}

// ---------------------------------------------------------------------------
// Kernel 1: horizontal pass, HR=4 rows per block, + pad fill + dtype probe.
// Grid: (H/HR + 2*PAD, B), 256 threads; thread t -> pixels [8t, 8t+8) of all
// 4 rows (4 independent vector loads -> MLP 4, one sync per 4 rows).
// d = min(clz(L | Rv), 22);  L = fsl(Wm,W0,31-p), Rv = fsl(brev Wp, brev W0, p).
// ---------------------------------------------------------------------------
__global__ void __launch_bounds__(256) hpass_kernel(const void* __restrict__ in_raw, int H)
{
    const int t  = threadIdx.x;
    const int bx = blockIdx.x;
    const int b  = blockIdx.y;

    if (bx < 2 * PAD) {                     // pad-fill block (one pad row each)
        const int row = (bx < PAD) ? bx : (PAD + W + (bx - PAD));
        unsigned short* p = g_dh2 + ((size_t)b * PSTRIDE + row) * W + (size_t)t * 8;
        const unsigned v = PADVAL | (PADVAL << 16);
        *(uint4*)p = make_uint4(v, v, v, v);
        return;
    }
    const int y0 = (bx - 2 * PAD) * HR;

    __shared__ unsigned int bits[HR * 64];  // HR rows x 64 words
    __shared__ int s_dt;

    if (t < 32) {
        unsigned v = __ldg((const unsigned int*)in_raw + t);
        unsigned any_mid = __ballot_sync(0xffffffffu, (v & 0x00FFFF00u) != 0);
        unsigned any_big = __ballot_sync(0xffffffffu, (v & 0xFEFEFEFEu) != 0);
        if (t == 0) s_dt = any_big ? 2 : (any_mid ? 0 : 1);   // 2=f32, 0=u8, 1=i32
    }
    __syncthreads();
    const int dt = s_dt;

    const size_t e0 = ((size_t)b * H + y0) * W + (size_t)t * 8;

    unsigned m[HR];
    if (dt == 1) {
        #pragma unroll
        for (int rr = 0; rr < HR; ++rr) {
            const int4* p = (const int4*)((const int*)in_raw + e0 + (size_t)rr * W);
            int4 a = __ldcs(p), c = __ldcs(p + 1);
            m[rr] = (a.x != 0) | ((a.y != 0) << 1) | ((a.z != 0) << 2) | ((a.w != 0) << 3)
                  | ((c.x != 0) << 4) | ((c.y != 0) << 5) | ((c.z != 0) << 6) | ((c.w != 0) << 7);
        }
    } else if (dt == 0) {
        #pragma unroll
        for (int rr = 0; rr < HR; ++rr) {
            unsigned long long v = __ldcs((const unsigned long long*)
                                          ((const unsigned char*)in_raw + e0 + (size_t)rr * W));
            unsigned mm = 0;
            #pragma unroll
            for (int j = 0; j < 8; ++j)
                mm |= (((v >> (8 * j)) & 0xFFull) != 0) << j;
            m[rr] = mm;
        }
    } else {
        #pragma unroll
        for (int rr = 0; rr < HR; ++rr) {
            const float4* p = (const float4*)((const float*)in_raw + e0 + (size_t)rr * W);
            float4 a = __ldcs(p), c = __ldcs(p + 1);
            m[rr] = (a.x != 0.f) | ((a.y != 0.f) << 1) | ((a.z != 0.f) << 2) | ((a.w != 0.f) << 3)
                  | ((c.x != 0.f) << 4) | ((c.y != 0.f) << 5) | ((c.z != 0.f) << 6) | ((c.w != 0.f) << 7);
        }
    }
    #pragma unroll
    for (int rr = 0; rr < HR; ++rr)
        ((unsigned char*)bits)[rr * 256 + t] = (unsigned char)m[rr];
    __syncthreads();

    const int wi = t >> 2;
    const int sh = (t & 3) * 8;

    unsigned short* outp = g_dh2 + ((size_t)b * PSTRIDE + PAD + y0) * W + (size_t)t * 8;

    #pragma unroll
    for (int rr = 0; rr < HR; ++rr) {
        const unsigned int* rowbits = bits + rr * 64;
        const unsigned int W0 = rowbits[wi];
        const unsigned int Wm = (wi > 0)  ? rowbits[wi - 1] : 0u;
        const unsigned int Wp = (wi < 63) ? rowbits[wi + 1] : 0u;
        const unsigned int rW0 = __brev(W0);
        const unsigned int rWp = __brev(Wp);

        unsigned int q[4];
        #pragma unroll
        for (int jj = 0; jj < 4; ++jj) {
            const int p0 = sh + 2 * jj;
            unsigned wL0 = __funnelshift_l(Wm,  W0,  31 - p0);
            unsigned wR0 = __funnelshift_l(rWp, rW0, p0);
            int d0 = min(__clz(wL0 | wR0), 22);

            const int p1 = p0 + 1;
            unsigned wL1 = __funnelshift_l(Wm,  W0,  31 - p1);
            unsigned wR1 = __funnelshift_l(rWp, rW0, p1);
            int d1 = min(__clz(wL1 | wR1), 22);

            q[jj] = (unsigned)(d0 * d0) | ((unsigned)(d1 * d1) << 16);
        }
        *(uint4*)(outp + (size_t)rr * W) = make_uint4(q[0], q[1], q[2], q[3]);
    }
}

// ---------------------------------------------------------------------------
// Kernel 2: vertical pass, strip-mined R=8 x PX=4. Grid (W/(256*PX), H/R, B).
// Center rows loaded once, cross-relaxed; bound bm0 computed ONCE after the
// center + k=1 relax, then k=2..21 runs while k^2 < bm0 with no per-iteration
// exit tree (bm0 >= bm_current, so this never stops earlier than the adaptive
// exit; extra taps are valid candidates and cannot change the min).
// ---------------------------------------------------------------------------
__global__ void __launch_bounds__(256, 6) vpass_kernel(float* __restrict__ out,
                                                       const float* __restrict__ max_sq,
                                                       int H)
{
    __shared__ float lut[512];
    const int t = threadIdx.x;
    lut[t]       = sqrtf((float)t);
    lut[t + 256] = sqrtf((float)(t + 256));
    __syncthreads();

    const int x0 = (blockIdx.x * 256 + t) * PX;
    const int y0 = blockIdx.y * R;
    const int b  = blockIdx.z;

    const unsigned short* gp = g_dh2 + ((size_t)b * PSTRIDE + PAD + y0) * W + x0;

    unsigned acc[R][2];
    #pragma unroll
    for (int j = 0; j < R; ++j)
        acc[j][0] = acc[j][1] = 0xFFFFFFFFu;

    // Center rows: load each once, relax every accumulator (dd = (r-j)^2).
    #pragma unroll
    for (int r = 0; r < R; ++r) {
        uint2 v = *(const uint2*)(gp + (size_t)r * W);
        #pragma unroll
        for (int j = 0; j < R; ++j) {
            const int d = r - j;
            relax2(acc[j], v, (unsigned)(d * d));
        }
    }

    // k = 1 unconditional.
    {
        uint2 u = *(const uint2*)(gp - (size_t)1 * W);
        uint2 v = *(const uint2*)(gp + (size_t)R * W);
        #pragma unroll
        for (int j = 0; j < R; ++j) {
            int du = 1 + j, dv = R - j;
            relax2(acc[j], u, (unsigned)(du * du));
            relax2(acc[j], v, (unsigned)(dv * dv));
        }
    }

    // Fixed bound: thread max after center + k=1.
    unsigned mm = 0;
    #pragma unroll
    for (int j = 0; j < R; ++j)
        mm = vmax2(mm, vmax2(acc[j][0], acc[j][1]));
    const int bm0 = max((int)(mm >> 16), (int)(mm & 0xFFFFu));

    #pragma unroll 1
    for (int k = 2; k <= 21 && k * k < bm0; ++k) {
        uint2 u = *(const uint2*)(gp - (size_t)k * W);
        uint2 v = *(const uint2*)(gp + (size_t)(R - 1 + k) * W);
        #pragma unroll
        for (int j = 0; j < R; ++j) {
            int du = k + j, dv = k + (R - 1 - j);
            relax2(acc[j], u, (unsigned)(du * du));
            relax2(acc[j], v, (unsigned)(dv * dv));
        }
    }

    const unsigned capu = min((unsigned)__ldg(max_sq), 511u);   // 441
    const unsigned capv = capu * 0x00010001u;

    float* o = out + ((size_t)b * H + y0) * W + x0;
    #pragma unroll
    for (int j = 0; j < R; ++j) {
        unsigned a0 = vmin2(acc[j][0], capv), a1 = vmin2(acc[j][1], capv);
        float4 r0;
        r0.x = lut[a0 & 0xFFFFu];  r0.y = lut[a0 >> 16];
        r0.z = lut[a1 & 0xFFFFu];  r0.w = lut[a1 >> 16];
        __stcs((float4*)(o + (size_t)j * W), r0);
    }
}

// ---------------------------------------------------------------------------
// Launch
// ---------------------------------------------------------------------------
extern "C" void kernel_launch(void* const* d_in, const int* in_sizes, int n_in,
                              void* d_out, int out_size)
{
    const void*  in     = d_in[0];
    const float* max_sq = (const float*)d_in[1];
    float*       out    = (float*)d_out;

    const int total = in_sizes[0];          // B*H*W
    const int B     = total / (W * W);      // 4
    const int H     = (total / W) / B;      // 2048

    hpass_kernel<<<dim3(H / HR + 2 * PAD, B), 256>>>(in, H);
    vpass_kernel<<<dim3(W / (256 * PX), H / R, B), 256>>>(out, max_sq, H);
}

// round 12
// speedup vs baseline: 1.0564x; 1.0564x over previous
#include <cuda_runtime.h>
#include <cstdint>

static constexpr int W       = 2048;
static constexpr int PAD     = 24;                 // >= 21 + strip slack
static constexpr int PSTRIDE = W + 2 * PAD;        // 2096 rows per plane
static constexpr unsigned PADVAL = 60000;          // 60000 + 841 < 65535
static constexpr int R       = 8;                  // vpass rows per thread
static constexpr int PX      = 2;                  // vpass pixels per thread

__device__ unsigned short g_dh2[4ULL * PSTRIDE * W];   // ~34 MB squared horiz dist (u16)

// ---- SIMD u16x2 helpers ----
__device__ __forceinline__ unsigned vadd2(unsigned a, unsigned b)
{ unsigned r; asm("add.u16x2 %0,%1,%2;" : "=r"(r) : "r"(a), "r"(b)); return r; }
__device__ __forceinline__ unsigned vmin2(unsigned a, unsigned b)
{ unsigned r; asm("min.u16x2 %0,%1,%2;" : "=r"(r) : "r"(a), "r"(b)); return r; }
__device__ __forceinline__ unsigned vmax2(unsigned a, unsigned b)
{ unsigned r; asm("max.u16x2 %0,%1,%2;" : "=r"(r) : "r"(a), "r"(b)); return r; }

// ---------------------------------------------------------------------------
// Kernel 1: horizontal pass, 2 rows per block, + pad fill + dtype probe.
// (Measured-best configuration from R10.)
// Grid: (H/2 + 2*PAD, B), 256 threads; thread t -> pixels [8t, 8t+8) of both rows.
// d = min(clz(L | Rv), 22);  L = fsl(Wm,W0,31-p), Rv = fsl(brev Wp, brev W0, p).
// ---------------------------------------------------------------------------
__global__ void __launch_bounds__(256) hpass_kernel(const void* __restrict__ in_raw, int H)
{
    const int t  = threadIdx.x;
    const int bx = blockIdx.x;
    const int b  = blockIdx.y;

    if (bx < 2 * PAD) {                     // pad-fill block (one pad row each)
        const int row = (bx < PAD) ? bx : (PAD + W + (bx - PAD));
        unsigned short* p = g_dh2 + ((size_t)b * PSTRIDE + row) * W + (size_t)t * 8;
        const unsigned v = PADVAL | (PADVAL << 16);
        *(uint4*)p = make_uint4(v, v, v, v);
        return;
    }
    const int y0 = (bx - 2 * PAD) * 2;

    __shared__ unsigned int bits[128];      // 2 rows x 64 words
    __shared__ int s_dt;

    if (t < 32) {
        unsigned v = __ldg((const unsigned int*)in_raw + t);
        unsigned any_mid = __ballot_sync(0xffffffffu, (v & 0x00FFFF00u) != 0);
        unsigned any_big = __ballot_sync(0xffffffffu, (v & 0xFEFEFEFEu) != 0);
        if (t == 0) s_dt = any_big ? 2 : (any_mid ? 0 : 1);   // 2=f32, 0=u8, 1=i32
    }
    __syncthreads();
    const int dt = s_dt;

    const size_t e0 = ((size_t)b * H + y0) * W + (size_t)t * 8;

    unsigned m0 = 0, m1 = 0;
    if (dt == 1) {
        const int4* p0 = (const int4*)((const int*)in_raw + e0);
        const int4* p1 = (const int4*)((const int*)in_raw + e0 + W);
        int4 a = __ldcs(p0), c = __ldcs(p0 + 1);
        int4 d = __ldcs(p1), e = __ldcs(p1 + 1);
        m0 = (a.x != 0) | ((a.y != 0) << 1) | ((a.z != 0) << 2) | ((a.w != 0) << 3)
           | ((c.x != 0) << 4) | ((c.y != 0) << 5) | ((c.z != 0) << 6) | ((c.w != 0) << 7);
        m1 = (d.x != 0) | ((d.y != 0) << 1) | ((d.z != 0) << 2) | ((d.w != 0) << 3)
           | ((e.x != 0) << 4) | ((e.y != 0) << 5) | ((e.z != 0) << 6) | ((e.w != 0) << 7);
    } else if (dt == 0) {
        unsigned long long v0 = __ldcs((const unsigned long long*)((const unsigned char*)in_raw + e0));
        unsigned long long v1 = __ldcs((const unsigned long long*)((const unsigned char*)in_raw + e0 + W));
        #pragma unroll
        for (int j = 0; j < 8; ++j) {
            m0 |= (((v0 >> (8 * j)) & 0xFFull) != 0) << j;
            m1 |= (((v1 >> (8 * j)) & 0xFFull) != 0) << j;
        }
    } else {
        const float4* p0 = (const float4*)((const float*)in_raw + e0);
        const float4* p1 = (const float4*)((const float*)in_raw + e0 + W);
        float4 a = __ldcs(p0), c = __ldcs(p0 + 1);
        float4 d = __ldcs(p1), e = __ldcs(p1 + 1);
        m0 = (a.x != 0.f) | ((a.y != 0.f) << 1) | ((a.z != 0.f) << 2) | ((a.w != 0.f) << 3)
           | ((c.x != 0.f) << 4) | ((c.y != 0.f) << 5) | ((c.z != 0.f) << 6) | ((c.w != 0.f) << 7);
        m1 = (d.x != 0.f) | ((d.y != 0.f) << 1) | ((d.z != 0.f) << 2) | ((d.w != 0.f) << 3)
           | ((e.x != 0.f) << 4) | ((e.y != 0.f) << 5) | ((e.z != 0.f) << 6) | ((e.w != 0.f) << 7);
    }
    ((unsigned char*)bits)[t]       = (unsigned char)m0;
    ((unsigned char*)bits)[t + 256] = (unsigned char)m1;
    __syncthreads();

    const int wi = t >> 2;
    const int sh = (t & 3) * 8;

    unsigned short* outp = g_dh2 + ((size_t)b * PSTRIDE + PAD + y0) * W + (size_t)t * 8;

    #pragma unroll
    for (int rr = 0; rr < 2; ++rr) {
        const unsigned int* rowbits = bits + rr * 64;
        const unsigned int W0 = rowbits[wi];
        const unsigned int Wm = (wi > 0)  ? rowbits[wi - 1] : 0u;
        const unsigned int Wp = (wi < 63) ? rowbits[wi + 1] : 0u;
        const unsigned int rW0 = __brev(W0);
        const unsigned int rWp = __brev(Wp);

        unsigned int q[4];
        #pragma unroll
        for (int jj = 0; jj < 4; ++jj) {
            const int p0 = sh + 2 * jj;
            unsigned wL0 = __funnelshift_l(Wm,  W0,  31 - p0);
            unsigned wR0 = __funnelshift_l(rWp, rW0, p0);
            int d0 = min(__clz(wL0 | wR0), 22);

            const int p1 = p0 + 1;
            unsigned wL1 = __funnelshift_l(Wm,  W0,  31 - p1);
            unsigned wR1 = __funnelshift_l(rWp, rW0, p1);
            int d1 = min(__clz(wL1 | wR1), 22);

            q[jj] = (unsigned)(d0 * d0) | ((unsigned)(d1 * d1) << 16);
        }
        *(uint4*)(outp + (size_t)rr * W) = make_uint4(q[0], q[1], q[2], q[3]);
    }
}

// ---------------------------------------------------------------------------
// Kernel 2: vertical pass, strip-mined R=8 x PX=2. Grid (W/(256*PX), H/R, B).
// One u32 (2 px) per row tap; 8 single-word accumulators. Bound bm0 computed
// once after center + k=1 relax; k=2..21 runs while k^2 < bm0 with no
// per-iteration exit tree (never stops earlier than the adaptive exit; extra
// taps are valid candidates of the min). High occupancy: 8 blocks/SM.
// ---------------------------------------------------------------------------
__global__ void __launch_bounds__(256, 8) vpass_kernel(float* __restrict__ out,
                                                       const float* __restrict__ max_sq,
                                                       int H)
{
    __shared__ float lut[512];
    const int t = threadIdx.x;
    lut[t]       = sqrtf((float)t);
    lut[t + 256] = sqrtf((float)(t + 256));
    __syncthreads();

    const int x0 = (blockIdx.x * 256 + t) * PX;
    const int y0 = blockIdx.y * R;
    const int b  = blockIdx.z;

    const unsigned short* gp = g_dh2 + ((size_t)b * PSTRIDE + PAD + y0) * W + x0;

    unsigned acc[R];
    #pragma unroll
    for (int j = 0; j < R; ++j) acc[j] = 0xFFFFFFFFu;

    // Center rows: load each once, relax every accumulator (dd = (r-j)^2).
    #pragma unroll
    for (int r = 0; r < R; ++r) {
        unsigned v = *(const unsigned*)(gp + (size_t)r * W);
        #pragma unroll
        for (int j = 0; j < R; ++j) {
            const int d = r - j;
            acc[j] = vmin2(acc[j], vadd2(v, (unsigned)(d * d) * 0x00010001u));
        }
    }

    // k = 1 unconditional.
    {
        unsigned u = *(const unsigned*)(gp - (size_t)1 * W);
        unsigned v = *(const unsigned*)(gp + (size_t)R * W);
        #pragma unroll
        for (int j = 0; j < R; ++j) {
            int du = 1 + j, dv = R - j;
            acc[j] = vmin2(acc[j], vadd2(u, (unsigned)(du * du) * 0x00010001u));
            acc[j] = vmin2(acc[j], vadd2(v, (unsigned)(dv * dv) * 0x00010001u));
        }
    }

    // Fixed bound: thread max after center + k=1.
    unsigned mm = 0;
    #pragma unroll
    for (int j = 0; j < R; ++j) mm = vmax2(mm, acc[j]);
    const int bm0 = max((int)(mm >> 16), (int)(mm & 0xFFFFu));

    #pragma unroll 1
    for (int k = 2; k <= 21 && k * k < bm0; ++k) {
        unsigned u = *(const unsigned*)(gp - (size_t)k * W);
        unsigned v = *(const unsigned*)(gp + (size_t)(R - 1 + k) * W);
        #pragma unroll
        for (int j = 0; j < R; ++j) {
            int du = k + j, dv = k + (R - 1 - j);
            acc[j] = vmin2(acc[j], vadd2(u, (unsigned)(du * du) * 0x00010001u));
            acc[j] = vmin2(acc[j], vadd2(v, (unsigned)(dv * dv) * 0x00010001u));
        }
    }

    const unsigned capu = min((unsigned)__ldg(max_sq), 511u);   // 441
    const unsigned capv = capu * 0x00010001u;

    float* o = out + ((size_t)b * H + y0) * W + x0;
    #pragma unroll
    for (int j = 0; j < R; ++j) {
        unsigned a0 = vmin2(acc[j], capv);
        float2 r0;
        r0.x = lut[a0 & 0xFFFFu];
        r0.y = lut[a0 >> 16];
        __stcs((float2*)(o + (size_t)j * W), r0);
    }
}

// ---------------------------------------------------------------------------
// Launch
// ---------------------------------------------------------------------------
extern "C" void kernel_launch(void* const* d_in, const int* in_sizes, int n_in,
                              void* d_out, int out_size)
{
    const void*  in     = d_in[0];
    const float* max_sq = (const float*)d_in[1];
    float*       out    = (float*)d_out;

    const int total = in_sizes[0];          // B*H*W
    const int B     = total / (W * W);      // 4
    const int H     = (total / W) / B;      // 2048

    hpass_kernel<<<dim3(H / 2 + 2 * PAD, B), 256>>>(in, H);
    vpass_kernel<<<dim3(W / (256 * PX), H / R, B), 256>>>(out, max_sq, H);
}

// round 13
// speedup vs baseline: 1.0626x; 1.0059x over previous
#include <cuda_runtime.h>
#include <cstdint>

static constexpr int W       = 2048;
static constexpr int PAD     = 24;                 // >= 21 + strip slack
static constexpr int PSTRIDE = W + 2 * PAD;        // 2096 rows per plane
static constexpr unsigned PADVAL = 60000;          // 60000 + 576 < 65535
static constexpr int R       = 4;                  // vpass rows per thread
static constexpr int PX      = 4;                  // vpass pixels per thread

__device__ unsigned short g_dh2[4ULL * PSTRIDE * W];   // ~34 MB squared horiz dist (u16)

// ---- SIMD u16x2 helpers ----
__device__ __forceinline__ unsigned vadd2(unsigned a, unsigned b)
{ unsigned r; asm("add.u16x2 %0,%1,%2;" : "=r"(r) : "r"(a), "r"(b)); return r; }
__device__ __forceinline__ unsigned vmin2(unsigned a, unsigned b)
{ unsigned r; asm("min.u16x2 %0,%1,%2;" : "=r"(r) : "r"(a), "r"(b)); return r; }
__device__ __forceinline__ unsigned vmax2(unsigned a, unsigned b)
{ unsigned r; asm("max.u16x2 %0,%1,%2;" : "=r"(r) : "r"(a), "r"(b)); return r; }

__device__ __forceinline__ void relax2(unsigned acc[2], const uint2& v, unsigned dd)
{
    const unsigned dd2 = dd * 0x00010001u;
    acc[0] = vmin2(acc[0], vadd2(v.x, dd2));
    acc[1] = vmin2(acc[1], vadd2(v.y, dd2));
}

// ---------------------------------------------------------------------------
// Kernel 1: horizontal pass, 2 rows per block, + pad fill + dtype probe.
// (Measured-best configuration.)
// ---------------------------------------------------------------------------
__global__ void __launch_bounds__(256) hpass_kernel(const void* __restrict__ in_raw, int H)
{
    const int t  = threadIdx.x;
    const int bx = blockIdx.x;
    const int b  = blockIdx.y;

    if (bx < 2 * PAD) {                     // pad-fill block (one pad row each)
        const int row = (bx < PAD) ? bx : (PAD + W + (bx - PAD));
        unsigned short* p = g_dh2 + ((size_t)b * PSTRIDE + row) * W + (size_t)t * 8;
        const unsigned v = PADVAL | (PADVAL << 16);
        *(uint4*)p = make_uint4(v, v, v, v);
        return;
    }
    const int y0 = (bx - 2 * PAD) * 2;

    __shared__ unsigned int bits[128];      // 2 rows x 64 words
    __shared__ int s_dt;

    if (t < 32) {
        unsigned v = __ldg((const unsigned int*)in_raw + t);
        unsigned any_mid = __ballot_sync(0xffffffffu, (v & 0x00FFFF00u) != 0);
        unsigned any_big = __ballot_sync(0xffffffffu, (v & 0xFEFEFEFEu) != 0);
        if (t == 0) s_dt = any_big ? 2 : (any_mid ? 0 : 1);   // 2=f32, 0=u8, 1=i32
    }
    __syncthreads();
    const int dt = s_dt;

    const size_t e0 = ((size_t)b * H + y0) * W + (size_t)t * 8;

    unsigned m0 = 0, m1 = 0;
    if (dt == 1) {
        const int4* p0 = (const int4*)((const int*)in_raw + e0);
        const int4* p1 = (const int4*)((const int*)in_raw + e0 + W);
        int4 a = __ldcs(p0), c = __ldcs(p0 + 1);
        int4 d = __ldcs(p1), e = __ldcs(p1 + 1);
        m0 = (a.x != 0) | ((a.y != 0) << 1) | ((a.z != 0) << 2) | ((a.w != 0) << 3)
           | ((c.x != 0) << 4) | ((c.y != 0) << 5) | ((c.z != 0) << 6) | ((c.w != 0) << 7);
        m1 = (d.x != 0) | ((d.y != 0) << 1) | ((d.z != 0) << 2) | ((d.w != 0) << 3)
           | ((e.x != 0) << 4) | ((e.y != 0) << 5) | ((e.z != 0) << 6) | ((e.w != 0) << 7);
    } else if (dt == 0) {
        unsigned long long v0 = __ldcs((const unsigned long long*)((const unsigned char*)in_raw + e0));
        unsigned long long v1 = __ldcs((const unsigned long long*)((const unsigned char*)in_raw + e0 + W));
        #pragma unroll
        for (int j = 0; j < 8; ++j) {
            m0 |= (((v0 >> (8 * j)) & 0xFFull) != 0) << j;
            m1 |= (((v1 >> (8 * j)) & 0xFFull) != 0) << j;
        }
    } else {
        const float4* p0 = (const float4*)((const float*)in_raw + e0);
        const float4* p1 = (const float4*)((const float*)in_raw + e0 + W);
        float4 a = __ldcs(p0), c = __ldcs(p0 + 1);
        float4 d = __ldcs(p1), e = __ldcs(p1 + 1);
        m0 = (a.x != 0.f) | ((a.y != 0.f) << 1) | ((a.z != 0.f) << 2) | ((a.w != 0.f) << 3)
           | ((c.x != 0.f) << 4) | ((c.y != 0.f) << 5) | ((c.z != 0.f) << 6) | ((c.w != 0.f) << 7);
        m1 = (d.x != 0.f) | ((d.y != 0.f) << 1) | ((d.z != 0.f) << 2) | ((d.w != 0.f) << 3)
           | ((e.x != 0.f) << 4) | ((e.y != 0.f) << 5) | ((e.z != 0.f) << 6) | ((e.w != 0.f) << 7);
    }
    ((unsigned char*)bits)[t]       = (unsigned char)m0;
    ((unsigned char*)bits)[t + 256] = (unsigned char)m1;
    __syncthreads();

    const int wi = t >> 2;
    const int sh = (t & 3) * 8;

    unsigned short* outp = g_dh2 + ((size_t)b * PSTRIDE + PAD + y0) * W + (size_t)t * 8;

    #pragma unroll
    for (int rr = 0; rr < 2; ++rr) {
        const unsigned int* rowbits = bits + rr * 64;
        const unsigned int W0 = rowbits[wi];
        const unsigned int Wm = (wi > 0)  ? rowbits[wi - 1] : 0u;
        const unsigned int Wp = (wi < 63) ? rowbits[wi + 1] : 0u;
        const unsigned int rW0 = __brev(W0);
        const unsigned int rWp = __brev(Wp);

        unsigned int q[4];
        #pragma unroll
        for (int jj = 0; jj < 4; ++jj) {
            const int p0 = sh + 2 * jj;
            unsigned wL0 = __funnelshift_l(Wm,  W0,  31 - p0);
            unsigned wR0 = __funnelshift_l(rWp, rW0, p0);
            int d0 = min(__clz(wL0 | wR0), 22);

            const int p1 = p0 + 1;
            unsigned wL1 = __funnelshift_l(Wm,  W0,  31 - p1);
            unsigned wR1 = __funnelshift_l(rWp, rW0, p1);
            int d1 = min(__clz(wL1 | wR1), 22);

            q[jj] = (unsigned)(d0 * d0) | ((unsigned)(d1 * d1) << 16);
        }
        *(uint4*)(outp + (size_t)rr * W) = make_uint4(q[0], q[1], q[2], q[3]);
    }
}

// ---------------------------------------------------------------------------
// Kernel 2: vertical pass, strip-mined R=4 x PX=4. Grid (W/(256*PX), H/R, B).
// Smaller strip => only 4 forced center taps + 2 k=1 taps per pixel (vs 10 at
// R=8), cutting the dominant ALU block ~25%. Bound bm0 computed once after
// center + k=1; k=2..21 runs while k^2 < bm0 (never stops earlier than the
// adaptive exit; extra taps are valid candidates of the min).
// ---------------------------------------------------------------------------
__global__ void __launch_bounds__(256, 8) vpass_kernel(float* __restrict__ out,
                                                       const float* __restrict__ max_sq,
                                                       int H)
{
    __shared__ float lut[512];
    const int t = threadIdx.x;
    lut[t]       = sqrtf((float)t);
    lut[t + 256] = sqrtf((float)(t + 256));
    __syncthreads();

    const int x0 = (blockIdx.x * 256 + t) * PX;
    const int y0 = blockIdx.y * R;
    const int b  = blockIdx.z;

    const unsigned short* gp = g_dh2 + ((size_t)b * PSTRIDE + PAD + y0) * W + x0;

    unsigned acc[R][2];
    #pragma unroll
    for (int j = 0; j < R; ++j)
        acc[j][0] = acc[j][1] = 0xFFFFFFFFu;

    // Center rows: load each once, relax every accumulator (dd = (r-j)^2 <= 9).
    #pragma unroll
    for (int r = 0; r < R; ++r) {
        uint2 v = *(const uint2*)(gp + (size_t)r * W);
        #pragma unroll
        for (int j = 0; j < R; ++j) {
            const int d = r - j;
            relax2(acc[j], v, (unsigned)(d * d));
        }
    }

    // k = 1 unconditional.
    {
        uint2 u = *(const uint2*)(gp - (size_t)1 * W);
        uint2 v = *(const uint2*)(gp + (size_t)R * W);
        #pragma unroll
        for (int j = 0; j < R; ++j) {
            int du = 1 + j, dv = R - j;
            relax2(acc[j], u, (unsigned)(du * du));
            relax2(acc[j], v, (unsigned)(dv * dv));
        }
    }

    // Fixed bound: thread max after center + k=1.
    unsigned mm = 0;
    #pragma unroll
    for (int j = 0; j < R; ++j)
        mm = vmax2(mm, vmax2(acc[j][0], acc[j][1]));
    const int bm0 = max((int)(mm >> 16), (int)(mm & 0xFFFFu));

    #pragma unroll 1
    for (int k = 2; k <= 21 && k * k < bm0; ++k) {
        uint2 u = *(const uint2*)(gp - (size_t)k * W);
        uint2 v = *(const uint2*)(gp + (size_t)(R - 1 + k) * W);
        #pragma unroll
        for (int j = 0; j < R; ++j) {
            int du = k + j, dv = k + (R - 1 - j);
            relax2(acc[j], u, (unsigned)(du * du));
            relax2(acc[j], v, (unsigned)(dv * dv));
        }
    }

    const unsigned capu = min((unsigned)__ldg(max_sq), 511u);   // 441
    const unsigned capv = capu * 0x00010001u;

    float* o = out + ((size_t)b * H + y0) * W + x0;
    #pragma unroll
    for (int j = 0; j < R; ++j) {
        unsigned a0 = vmin2(acc[j][0], capv), a1 = vmin2(acc[j][1], capv);
        float4 r0;
        r0.x = lut[a0 & 0xFFFFu];  r0.y = lut[a0 >> 16];
        r0.z = lut[a1 & 0xFFFFu];  r0.w = lut[a1 >> 16];
        __stcs((float4*)(o + (size_t)j * W), r0);
    }
}

// ---------------------------------------------------------------------------
// Launch
// ---------------------------------------------------------------------------
extern "C" void kernel_launch(void* const* d_in, const int* in_sizes, int n_in,
                              void* d_out, int out_size)
{
    const void*  in     = d_in[0];
    const float* max_sq = (const float*)d_in[1];
    float*       out    = (float*)d_out;

    const int total = in_sizes[0];          // B*H*W
    const int B     = total / (W * W);      // 4
    const int H     = (total / W) / B;      // 2048

    hpass_kernel<<<dim3(H / 2 + 2 * PAD, B), 256>>>(in, H);
    vpass_kernel<<<dim3(W / (256 * PX), H / R, B), 256>>>(out, max_sq, H);
}